// round 1
// baseline (speedup 1.0000x reference)
#include <cuda_runtime.h>
#include <math.h>

#define N_USER  100000
#define N_ITEM  50000
#define DIM     64
#define N_BEH   3
#define NE      1000000
#define BATCH   4096
#define LN_EPS  1e-5f

// Scratch: per-user softmax denominators and per-item aggregation A
__device__ float g_S[N_BEH * N_USER];            // 1.2 MB
__device__ float g_A[(size_t)N_BEH * N_ITEM * DIM]; // 38.4 MB

// ---------------------------------------------------------------------------
// Zero scratch
// ---------------------------------------------------------------------------
__global__ void zero_kernel() {
    size_t total = (size_t)N_BEH * N_USER + (size_t)N_BEH * N_ITEM * DIM;
    for (size_t i = (size_t)blockIdx.x * blockDim.x + threadIdx.x;
         i < total; i += (size_t)gridDim.x * blockDim.x) {
        if (i < (size_t)N_BEH * N_USER) g_S[i] = 0.0f;
        else g_A[i - (size_t)N_BEH * N_USER] = 0.0f;
    }
}

// ---------------------------------------------------------------------------
// Pass A: per-edge act = elu(|ue-ie|.alpha_w + alpha_b), e = exp(act),
//         aux = sum(diff^2); atomic-sum e per user. One warp per edge.
// ---------------------------------------------------------------------------
__global__ void edge_act_kernel(const float* __restrict__ user_emb,
                                const float* __restrict__ item_emb,
                                const float* __restrict__ alpha_w,
                                const float* __restrict__ alpha_b,
                                const int*   __restrict__ edge_index,
                                float* __restrict__ tpw,
                                float* __restrict__ aux) {
    int gw = (blockIdx.x * blockDim.x + threadIdx.x) >> 5;
    int lane = threadIdx.x & 31;
    if (gw >= N_BEH * NE) return;
    int b = gw / NE;
    int e = gw - b * NE;
    const int* ei = edge_index + (size_t)b * 2 * NE;
    int u = ei[e];
    int i = ei[NE + e];

    const float2 ue = *(const float2*)&user_emb[(size_t)u * (N_BEH * DIM) + b * DIM + 2 * lane];
    const float2 ie = *(const float2*)&item_emb[(size_t)i * (N_BEH * DIM) + b * DIM + 2 * lane];
    float d0 = fabsf(ue.x - ie.x);
    float d1 = fabsf(ue.y - ie.y);
    float2 aw = *(const float2*)&alpha_w[b * DIM + 2 * lane];
    float z  = d0 * aw.x + d1 * aw.y;
    float a2 = d0 * d0 + d1 * d1;
    #pragma unroll
    for (int o = 16; o; o >>= 1) {
        z  += __shfl_xor_sync(0xffffffffu, z,  o);
        a2 += __shfl_xor_sync(0xffffffffu, a2, o);
    }
    if (lane == 0) {
        z += alpha_b[b];
        float act = (z > 0.0f) ? z : (expf(z) - 1.0f);  // elu, alpha=1
        float ev  = expf(act);                           // no max-shift needed (|act|<~12)
        tpw[(size_t)b * NE + e] = ev;
        aux[(size_t)b * NE + e] = a2;
        atomicAdd(&g_S[b * N_USER + u], ev);
    }
}

// ---------------------------------------------------------------------------
// Pass B: normalize tpw, and scatter A[b][item] += tpw * user_emb[u,b,:].
// 16 lanes (float4 granularity) per edge; 2 edges per warp.
// ---------------------------------------------------------------------------
__global__ void scatter_kernel(const float* __restrict__ user_emb,
                               const int*   __restrict__ edge_index,
                               float* __restrict__ tpw) {
    size_t gt = (size_t)blockIdx.x * blockDim.x + threadIdx.x;
    size_t gh = gt >> 4;        // edge id
    int l = (int)(gt & 15);
    if (gh >= (size_t)N_BEH * NE) return;
    int b = (int)(gh / NE);
    int e = (int)(gh - (size_t)b * NE);
    const int* ei = edge_index + (size_t)b * 2 * NE;
    int u = ei[e];
    int i = ei[NE + e];

    float w = tpw[(size_t)b * NE + e] / g_S[b * N_USER + u];
    if (l == 0) tpw[(size_t)b * NE + e] = w;

    float4 uv = *(const float4*)&user_emb[(size_t)u * (N_BEH * DIM) + b * DIM + 4 * l];
    float* dst = &g_A[((size_t)b * N_ITEM + i) * DIM + 4 * l];
    asm volatile("red.global.add.v4.f32 [%0], {%1,%2,%3,%4};"
                 :: "l"(dst), "f"(w * uv.x), "f"(w * uv.y),
                    "f"(w * uv.z), "f"(w * uv.w) : "memory");
}

// ---------------------------------------------------------------------------
// Pass C: per gathered row (12288): build x (3x64), qkv, 3x3x4-head attention,
// out-proj, residual, layernorm, sum over behaviors. 64-thread team per row,
// 4 teams per 256-thread block. Grid = 3072 exactly (no partial blocks).
// ---------------------------------------------------------------------------
#define TEAM_F 1216   // floats of scratch per team

__global__ void attn_kernel(const float* __restrict__ user_emb,
                            const float* __restrict__ item_emb,
                            const float* __restrict__ wq, const float* __restrict__ bq,
                            const float* __restrict__ wk, const float* __restrict__ bk,
                            const float* __restrict__ wv, const float* __restrict__ bv,
                            const float* __restrict__ wo, const float* __restrict__ bo,
                            const float* __restrict__ lng, const float* __restrict__ lnb,
                            const int* __restrict__ users,
                            const int* __restrict__ pos_items,
                            const int* __restrict__ neg_items,
                            float* __restrict__ emb_out) {
    __shared__ float sm[4 * TEAM_F];
    int team = threadIdx.x >> 6;
    int t    = threadIdx.x & 63;
    int row  = blockIdx.x * 4 + team;

    float* base = sm + team * TEAM_F;
    float* xs = base;          // [3*64]
    float* qs = base + 192;
    float* ks = base + 384;
    float* vs = base + 576;
    float* ao = base + 768;
    float* hh = base + 960;
    float* sc = base + 1152;   // [36] scores -> attn (in place)
    float* mus = base + 1188;  // [3]
    float* rss = base + 1191;  // [3]

    int node; bool is_user;
    if (row < BATCH)          { node = users[row];                 is_user = true;  }
    else if (row < 2 * BATCH) { node = pos_items[row - BATCH];     is_user = false; }
    else                      { node = neg_items[row - 2 * BATCH]; is_user = false; }

    // x rows: users = user_emb (GCN leaves them fixed); items = 2*A + item_emb
    #pragma unroll
    for (int beh = 0; beh < 3; beh++) {
        float v;
        if (is_user) {
            v = user_emb[(size_t)node * (N_BEH * DIM) + beh * DIM + t];
        } else {
            v = 2.0f * g_A[((size_t)beh * N_ITEM + node) * DIM + t]
                + item_emb[(size_t)node * (N_BEH * DIM) + beh * DIM + t];
        }
        xs[beh * 64 + t] = v;
    }
    __syncthreads();

    // q,k,v  (thread t owns output column t across all 3 behaviors)
    {
        float aq0 = bq[t], aq1 = aq0, aq2 = aq0;
        float ak0 = bk[t], ak1 = ak0, ak2 = ak0;
        float av0 = bv[t], av1 = av0, av2 = av0;
        #pragma unroll 8
        for (int d = 0; d < 64; d++) {
            float w1 = wq[d * 64 + t];
            float w2 = wk[d * 64 + t];
            float w3 = wv[d * 64 + t];
            float x0 = xs[d], x1 = xs[64 + d], x2 = xs[128 + d];
            aq0 += x0 * w1; aq1 += x1 * w1; aq2 += x2 * w1;
            ak0 += x0 * w2; ak1 += x1 * w2; ak2 += x2 * w2;
            av0 += x0 * w3; av1 += x1 * w3; av2 += x2 * w3;
        }
        qs[t] = aq0; qs[64 + t] = aq1; qs[128 + t] = aq2;
        ks[t] = ak0; ks[64 + t] = ak1; ks[128 + t] = ak2;
        vs[t] = av0; vs[64 + t] = av1; vs[128 + t] = av2;
    }
    __syncthreads();

    // scores: 4 heads x 3 q-beh x 3 k-beh, dh=16, scale 1/4
    if (t < 36) {
        int h  = t / 9;
        int qb = (t % 9) / 3;
        int kb = t % 3;
        float s = 0.0f;
        #pragma unroll
        for (int j = 0; j < 16; j++)
            s += qs[qb * 64 + h * 16 + j] * ks[kb * 64 + h * 16 + j];
        sc[t] = s * 0.25f;
    }
    __syncthreads();

    // softmax over kb (3 values) per (h,qb)
    if (t < 12) {
        int bidx = t * 3;
        float s0 = sc[bidx], s1 = sc[bidx + 1], s2 = sc[bidx + 2];
        float m = fmaxf(s0, fmaxf(s1, s2));
        float e0 = expf(s0 - m), e1 = expf(s1 - m), e2 = expf(s2 - m);
        float inv = 1.0f / (e0 + e1 + e2);
        sc[bidx] = e0 * inv; sc[bidx + 1] = e1 * inv; sc[bidx + 2] = e2 * inv;
    }
    __syncthreads();

    // att_out
    {
        int h = t >> 4;
        #pragma unroll
        for (int qb = 0; qb < 3; qb++) {
            float a = 0.0f;
            #pragma unroll
            for (int kb = 0; kb < 3; kb++)
                a += sc[h * 9 + qb * 3 + kb] * vs[kb * 64 + t];
            ao[qb * 64 + t] = a;
        }
    }
    __syncthreads();

    // out-proj + residual
    {
        float a0 = bo[t], a1 = a0, a2 = a0;
        #pragma unroll 8
        for (int d = 0; d < 64; d++) {
            float w = wo[d * 64 + t];
            a0 += ao[d] * w; a1 += ao[64 + d] * w; a2 += ao[128 + d] * w;
        }
        hh[t]       = a0 + xs[t];
        hh[64 + t]  = a1 + xs[64 + t];
        hh[128 + t] = a2 + xs[128 + t];
    }
    __syncthreads();

    // layernorm stats per behavior row
    if (t < 3) {
        float s = 0.0f;
        #pragma unroll 8
        for (int j = 0; j < 64; j++) s += hh[t * 64 + j];
        float mu = s * (1.0f / 64.0f);
        float v = 0.0f;
        #pragma unroll 8
        for (int j = 0; j < 64; j++) {
            float d = hh[t * 64 + j] - mu;
            v += d * d;
        }
        v *= (1.0f / 64.0f);
        mus[t] = mu;
        rss[t] = rsqrtf(v + LN_EPS);
    }
    __syncthreads();

    // normalize + sum over behaviors
    {
        float gg = lng[t], bb = lnb[t];
        float g = 0.0f;
        #pragma unroll
        for (int qb = 0; qb < 3; qb++)
            g += (hh[qb * 64 + t] - mus[qb]) * rss[qb] * gg + bb;
        emb_out[(size_t)row * 64 + t] = g;
    }
}

// ---------------------------------------------------------------------------
extern "C" void kernel_launch(void* const* d_in, const int* in_sizes, int n_in,
                              void* d_out, int out_size) {
    const float* user_emb = (const float*)d_in[0];
    const float* item_emb = (const float*)d_in[1];
    const float* alpha_w  = (const float*)d_in[2];
    const float* alpha_b  = (const float*)d_in[3];
    const float* wq = (const float*)d_in[4];
    const float* bq = (const float*)d_in[5];
    const float* wk = (const float*)d_in[6];
    const float* bk = (const float*)d_in[7];
    const float* wv = (const float*)d_in[8];
    const float* bv = (const float*)d_in[9];
    const float* wo = (const float*)d_in[10];
    const float* bo = (const float*)d_in[11];
    const float* lng = (const float*)d_in[12];
    const float* lnb = (const float*)d_in[13];
    const int* edge_index = (const int*)d_in[14];
    const int* users      = (const int*)d_in[15];
    const int* pos_items  = (const int*)d_in[16];
    const int* neg_items  = (const int*)d_in[17];

    float* out     = (float*)d_out;
    float* emb_out = out;                                // [3*BATCH, 64]
    float* tpw     = out + (size_t)3 * BATCH * DIM;      // [3, NE]
    float* aux     = tpw + (size_t)N_BEH * NE;           // [3, NE]

    zero_kernel<<<4096, 256>>>();

    // Pass A: 3e6 warps, 8 warps/block
    edge_act_kernel<<<(N_BEH * NE) / 8, 256>>>(user_emb, item_emb, alpha_w,
                                               alpha_b, edge_index, tpw, aux);

    // Pass B: 3e6 edges * 16 lanes / 256
    scatter_kernel<<<(size_t)N_BEH * NE * 16 / 256, 256>>>(user_emb, edge_index, tpw);

    // Pass C: 12288 rows, 4 rows/block
    attn_kernel<<<(3 * BATCH) / 4, 256>>>(user_emb, item_emb,
                                          wq, bq, wk, bk, wv, bv, wo, bo,
                                          lng, lnb, users, pos_items, neg_items,
                                          emb_out);
}

// round 2
// speedup vs baseline: 1.3664x; 1.3664x over previous
#include <cuda_runtime.h>
#include <math.h>

#define N_USER  100000
#define N_ITEM  50000
#define DIM     64
#define N_BEH   3
#define NE      1000000
#define BATCH   4096
#define LN_EPS  1e-5f

// Scratch
__device__ float g_S[N_BEH * N_USER];                 // softmax denominators
__device__ float g_A[(size_t)N_BEH * N_ITEM * DIM];   // per-item aggregation (38.4 MB)
__device__ int   g_mask[N_ITEM];                      // 1 if item appears in pos/neg

// ---------------------------------------------------------------------------
// Zero scratch (S, A, mask)
// ---------------------------------------------------------------------------
__global__ void zero_kernel() {
    // A as float4
    size_t nA4 = (size_t)N_BEH * N_ITEM * DIM / 4;
    float4* A4 = (float4*)g_A;
    for (size_t idx = (size_t)blockIdx.x * blockDim.x + threadIdx.x;
         idx < nA4; idx += (size_t)gridDim.x * blockDim.x)
        A4[idx] = make_float4(0.f, 0.f, 0.f, 0.f);
    for (size_t idx = (size_t)blockIdx.x * blockDim.x + threadIdx.x;
         idx < N_BEH * N_USER; idx += (size_t)gridDim.x * blockDim.x)
        g_S[idx] = 0.0f;
    for (size_t idx = (size_t)blockIdx.x * blockDim.x + threadIdx.x;
         idx < N_ITEM; idx += (size_t)gridDim.x * blockDim.x)
        g_mask[idx] = 0;
}

// ---------------------------------------------------------------------------
// Mark items that actually feed the output
// ---------------------------------------------------------------------------
__global__ void mask_kernel(const int* __restrict__ pos_items,
                            const int* __restrict__ neg_items) {
    int t = blockIdx.x * blockDim.x + threadIdx.x;
    if (t < BATCH) {
        g_mask[pos_items[t]] = 1;
        g_mask[neg_items[t]] = 1;
    }
}

// ---------------------------------------------------------------------------
// Pass A: 8 lanes per edge, 4 edges per warp. Computes
//   ev = exp(elu(|ue-ie|.alpha_w + alpha_b)), aux = sum(diff^2)
// and block-aggregates ev into g_S (sorted-u runs -> ~4 reds / 32 edges).
// ---------------------------------------------------------------------------
__global__ void edge_act_kernel(const float* __restrict__ user_emb,
                                const float* __restrict__ item_emb,
                                const float* __restrict__ alpha_w,
                                const float* __restrict__ alpha_b,
                                const int*   __restrict__ edge_index,
                                float* __restrict__ tpw,
                                float* __restrict__ aux) {
    __shared__ int   s_u[32];
    __shared__ float s_ev[32];

    int tid  = threadIdx.x;
    size_t g = (size_t)blockIdx.x * blockDim.x + tid;
    size_t e = g >> 3;                 // global edge id (0..3M)
    int sl   = tid & 7;                // sub-lane within edge
    int b    = (int)(e / NE);          // whole block shares b (NE % 32 == 0)
    int el   = (int)(e - (size_t)b * NE);

    const int* ei = edge_index + (size_t)b * 2 * NE;
    int u = ei[el];
    int i = ei[NE + el];

    const float4* up = (const float4*)&user_emb[(size_t)u * (N_BEH * DIM) + b * DIM + sl * 8];
    const float4* ip = (const float4*)&item_emb[(size_t)i * (N_BEH * DIM) + b * DIM + sl * 8];
    const float4* ap = (const float4*)&alpha_w[b * DIM + sl * 8];
    float4 u0 = up[0], u1 = up[1];
    float4 i0 = ip[0], i1 = ip[1];
    float4 a0 = ap[0], a1 = ap[1];

    float d;
    float z = 0.f, a2 = 0.f;
    d = fabsf(u0.x - i0.x); z += d * a0.x; a2 += d * d;
    d = fabsf(u0.y - i0.y); z += d * a0.y; a2 += d * d;
    d = fabsf(u0.z - i0.z); z += d * a0.z; a2 += d * d;
    d = fabsf(u0.w - i0.w); z += d * a0.w; a2 += d * d;
    d = fabsf(u1.x - i1.x); z += d * a1.x; a2 += d * d;
    d = fabsf(u1.y - i1.y); z += d * a1.y; a2 += d * d;
    d = fabsf(u1.z - i1.z); z += d * a1.z; a2 += d * d;
    d = fabsf(u1.w - i1.w); z += d * a1.w; a2 += d * d;

    #pragma unroll
    for (int o = 4; o; o >>= 1) {
        z  += __shfl_xor_sync(0xffffffffu, z,  o);
        a2 += __shfl_xor_sync(0xffffffffu, a2, o);
    }

    int slot = tid >> 3;               // 0..31 edge slot in block
    if (sl == 0) {
        z += alpha_b[b];
        float act = (z > 0.0f) ? z : (expf(z) - 1.0f);   // elu(alpha=1)
        float ev  = expf(act);                           // bounded, no max shift
        tpw[(size_t)b * NE + el] = ev;
        aux[(size_t)b * NE + el] = a2;
        s_u[slot]  = u;
        s_ev[slot] = ev;
    }
    __syncthreads();

    // warp 0 does segmented sums over the 32 sorted-u edges, one red per run
    if (tid < 32) {
        int myu = s_u[tid];
        bool head = (tid == 0) || (s_u[tid - 1] != myu);
        if (head) {
            float sum = s_ev[tid];
            #pragma unroll 4
            for (int k = tid + 1; k < 32 && s_u[k] == myu; k++) sum += s_ev[k];
            float* dst = &g_S[b * N_USER + myu];
            asm volatile("red.global.add.f32 [%0], %1;" :: "l"(dst), "f"(sum) : "memory");
        }
    }
}

// ---------------------------------------------------------------------------
// Pass B: normalize tpw (all edges); scatter A[b][item] += w * ue only for
// items that the output gathers (g_mask). 16 lanes per edge.
// ---------------------------------------------------------------------------
__global__ void scatter_kernel(const float* __restrict__ user_emb,
                               const int*   __restrict__ edge_index,
                               float* __restrict__ tpw) {
    size_t gt = (size_t)blockIdx.x * blockDim.x + threadIdx.x;
    size_t gh = gt >> 4;               // edge id
    int l = (int)(gt & 15);
    int b = (int)(gh / NE);
    int e = (int)(gh - (size_t)b * NE);
    const int* ei = edge_index + (size_t)b * 2 * NE;
    int u = ei[e];
    int i = ei[NE + e];

    float w = tpw[(size_t)b * NE + e] / g_S[b * N_USER + u];
    if (l == 0) tpw[(size_t)b * NE + e] = w;

    if (g_mask[i]) {
        float4 uv = *(const float4*)&user_emb[(size_t)u * (N_BEH * DIM) + b * DIM + 4 * l];
        float* dst = &g_A[((size_t)b * N_ITEM + i) * DIM + 4 * l];
        asm volatile("red.global.add.v4.f32 [%0], {%1,%2,%3,%4};"
                     :: "l"(dst), "f"(w * uv.x), "f"(w * uv.y),
                        "f"(w * uv.z), "f"(w * uv.w) : "memory");
    }
}

// ---------------------------------------------------------------------------
// Pass C: per gathered row (12288): x (3x64), qkv, 3x3x4-head attention,
// out-proj, residual, layernorm, sum over behaviors. 64-thread team per row.
// ---------------------------------------------------------------------------
#define TEAM_F 1216

__global__ void attn_kernel(const float* __restrict__ user_emb,
                            const float* __restrict__ item_emb,
                            const float* __restrict__ wq, const float* __restrict__ bq,
                            const float* __restrict__ wk, const float* __restrict__ bk,
                            const float* __restrict__ wv, const float* __restrict__ bv,
                            const float* __restrict__ wo, const float* __restrict__ bo,
                            const float* __restrict__ lng, const float* __restrict__ lnb,
                            const int* __restrict__ users,
                            const int* __restrict__ pos_items,
                            const int* __restrict__ neg_items,
                            float* __restrict__ emb_out) {
    __shared__ float sm[4 * TEAM_F];
    int team = threadIdx.x >> 6;
    int t    = threadIdx.x & 63;
    int row  = blockIdx.x * 4 + team;

    float* base = sm + team * TEAM_F;
    float* xs = base;
    float* qs = base + 192;
    float* ks = base + 384;
    float* vs = base + 576;
    float* ao = base + 768;
    float* hh = base + 960;
    float* sc = base + 1152;
    float* mus = base + 1188;
    float* rss = base + 1191;

    int node; bool is_user;
    if (row < BATCH)          { node = users[row];                 is_user = true;  }
    else if (row < 2 * BATCH) { node = pos_items[row - BATCH];     is_user = false; }
    else                      { node = neg_items[row - 2 * BATCH]; is_user = false; }

    #pragma unroll
    for (int beh = 0; beh < 3; beh++) {
        float v;
        if (is_user) {
            v = user_emb[(size_t)node * (N_BEH * DIM) + beh * DIM + t];
        } else {
            v = 2.0f * g_A[((size_t)beh * N_ITEM + node) * DIM + t]
                + item_emb[(size_t)node * (N_BEH * DIM) + beh * DIM + t];
        }
        xs[beh * 64 + t] = v;
    }
    __syncthreads();

    {
        float aq0 = bq[t], aq1 = aq0, aq2 = aq0;
        float ak0 = bk[t], ak1 = ak0, ak2 = ak0;
        float av0 = bv[t], av1 = av0, av2 = av0;
        #pragma unroll 8
        for (int d = 0; d < 64; d++) {
            float w1 = wq[d * 64 + t];
            float w2 = wk[d * 64 + t];
            float w3 = wv[d * 64 + t];
            float x0 = xs[d], x1 = xs[64 + d], x2 = xs[128 + d];
            aq0 += x0 * w1; aq1 += x1 * w1; aq2 += x2 * w1;
            ak0 += x0 * w2; ak1 += x1 * w2; ak2 += x2 * w2;
            av0 += x0 * w3; av1 += x1 * w3; av2 += x2 * w3;
        }
        qs[t] = aq0; qs[64 + t] = aq1; qs[128 + t] = aq2;
        ks[t] = ak0; ks[64 + t] = ak1; ks[128 + t] = ak2;
        vs[t] = av0; vs[64 + t] = av1; vs[128 + t] = av2;
    }
    __syncthreads();

    if (t < 36) {
        int h  = t / 9;
        int qb = (t % 9) / 3;
        int kb = t % 3;
        float s = 0.0f;
        #pragma unroll
        for (int j = 0; j < 16; j++)
            s += qs[qb * 64 + h * 16 + j] * ks[kb * 64 + h * 16 + j];
        sc[t] = s * 0.25f;
    }
    __syncthreads();

    if (t < 12) {
        int bidx = t * 3;
        float s0 = sc[bidx], s1 = sc[bidx + 1], s2 = sc[bidx + 2];
        float m = fmaxf(s0, fmaxf(s1, s2));
        float e0 = expf(s0 - m), e1 = expf(s1 - m), e2 = expf(s2 - m);
        float inv = 1.0f / (e0 + e1 + e2);
        sc[bidx] = e0 * inv; sc[bidx + 1] = e1 * inv; sc[bidx + 2] = e2 * inv;
    }
    __syncthreads();

    {
        int h = t >> 4;
        #pragma unroll
        for (int qb = 0; qb < 3; qb++) {
            float a = 0.0f;
            #pragma unroll
            for (int kb = 0; kb < 3; kb++)
                a += sc[h * 9 + qb * 3 + kb] * vs[kb * 64 + t];
            ao[qb * 64 + t] = a;
        }
    }
    __syncthreads();

    {
        float a0 = bo[t], a1 = a0, a2 = a0;
        #pragma unroll 8
        for (int d = 0; d < 64; d++) {
            float w = wo[d * 64 + t];
            a0 += ao[d] * w; a1 += ao[64 + d] * w; a2 += ao[128 + d] * w;
        }
        hh[t]       = a0 + xs[t];
        hh[64 + t]  = a1 + xs[64 + t];
        hh[128 + t] = a2 + xs[128 + t];
    }
    __syncthreads();

    if (t < 3) {
        float s = 0.0f;
        #pragma unroll 8
        for (int j = 0; j < 64; j++) s += hh[t * 64 + j];
        float mu = s * (1.0f / 64.0f);
        float v = 0.0f;
        #pragma unroll 8
        for (int j = 0; j < 64; j++) {
            float d = hh[t * 64 + j] - mu;
            v += d * d;
        }
        v *= (1.0f / 64.0f);
        mus[t] = mu;
        rss[t] = rsqrtf(v + LN_EPS);
    }
    __syncthreads();

    {
        float gg = lng[t], bb = lnb[t];
        float g = 0.0f;
        #pragma unroll
        for (int qb = 0; qb < 3; qb++)
            g += (hh[qb * 64 + t] - mus[qb]) * rss[qb] * gg + bb;
        emb_out[(size_t)row * 64 + t] = g;
    }
}

// ---------------------------------------------------------------------------
extern "C" void kernel_launch(void* const* d_in, const int* in_sizes, int n_in,
                              void* d_out, int out_size) {
    const float* user_emb = (const float*)d_in[0];
    const float* item_emb = (const float*)d_in[1];
    const float* alpha_w  = (const float*)d_in[2];
    const float* alpha_b  = (const float*)d_in[3];
    const float* wq = (const float*)d_in[4];
    const float* bq = (const float*)d_in[5];
    const float* wk = (const float*)d_in[6];
    const float* bk = (const float*)d_in[7];
    const float* wv = (const float*)d_in[8];
    const float* bv = (const float*)d_in[9];
    const float* wo = (const float*)d_in[10];
    const float* bo = (const float*)d_in[11];
    const float* lng = (const float*)d_in[12];
    const float* lnb = (const float*)d_in[13];
    const int* edge_index = (const int*)d_in[14];
    const int* users      = (const int*)d_in[15];
    const int* pos_items  = (const int*)d_in[16];
    const int* neg_items  = (const int*)d_in[17];

    float* out     = (float*)d_out;
    float* emb_out = out;
    float* tpw     = out + (size_t)3 * BATCH * DIM;
    float* aux     = tpw + (size_t)N_BEH * NE;

    zero_kernel<<<2048, 256>>>();
    mask_kernel<<<(BATCH + 255) / 256, 256>>>(pos_items, neg_items);

    // Pass A: 3M edges * 8 lanes / 256
    edge_act_kernel<<<(size_t)N_BEH * NE * 8 / 256, 256>>>(user_emb, item_emb,
                                                           alpha_w, alpha_b,
                                                           edge_index, tpw, aux);

    // Pass B: 3M edges * 16 lanes / 256
    scatter_kernel<<<(size_t)N_BEH * NE * 16 / 256, 256>>>(user_emb, edge_index, tpw);

    // Pass C
    attn_kernel<<<(3 * BATCH) / 4, 256>>>(user_emb, item_emb,
                                          wq, bq, wk, bk, wv, bv, wo, bo,
                                          lng, lnb, users, pos_items, neg_items,
                                          emb_out);
}

// round 3
// speedup vs baseline: 1.8992x; 1.3899x over previous
#include <cuda_runtime.h>
#include <math.h>

#define N_USER  100000
#define N_ITEM  50000
#define DIM     64
#define N_BEH   3
#define NE      1000000
#define NE_ALL  (N_BEH * NE)
#define BATCH   4096
#define LN_EPS  1e-5f

// Scratch
__device__ float g_S[N_BEH * N_USER];                 // softmax denominators
__device__ float g_A[(size_t)N_BEH * N_ITEM * DIM];   // per-item aggregation
__device__ int   g_mask[N_ITEM];                      // item feeds output?
__device__ int   g_cnt;                               // compacted edge count
__device__ int   g_cu[NE_ALL];                        // user_emb float offset
__device__ int   g_cib[NE_ALL];                       // g_A float offset (row base)
__device__ float g_cw[NE_ALL];                        // normalized weight

// ---------------------------------------------------------------------------
// Zero small scratch (S, mask, counter)
// ---------------------------------------------------------------------------
__global__ void zero_small_kernel() {
    int idx = blockIdx.x * blockDim.x + threadIdx.x;
    if (idx == 0) g_cnt = 0;
    for (int i = idx; i < N_BEH * N_USER; i += gridDim.x * blockDim.x)
        g_S[i] = 0.0f;
    for (int i = idx; i < N_ITEM; i += gridDim.x * blockDim.x)
        g_mask[i] = 0;
}

__global__ void mask_kernel(const int* __restrict__ pos_items,
                            const int* __restrict__ neg_items) {
    int t = blockIdx.x * blockDim.x + threadIdx.x;
    if (t < BATCH) {
        g_mask[pos_items[t]] = 1;
        g_mask[neg_items[t]] = 1;
    }
}

// Zero only the A rows that will be read (masked items). 16 float4 per row.
__global__ void zero_A_masked_kernel() {
    int idx = blockIdx.x * blockDim.x + threadIdx.x;   // over 3*N_ITEM*16
    int row = idx >> 4;
    if (row >= N_BEH * N_ITEM) return;
    int i = row % N_ITEM;
    if (g_mask[i]) {
        float4* dst = (float4*)&g_A[(size_t)row * DIM] + (idx & 15);
        *dst = make_float4(0.f, 0.f, 0.f, 0.f);
    }
}

// ---------------------------------------------------------------------------
// Pass A: 8 lanes per edge; ev = exp(elu(|ue-ie|.alpha_w + alpha_b)),
// aux = sum(diff^2); block-level segmented sum of ev into g_S.
// ---------------------------------------------------------------------------
__global__ void edge_act_kernel(const float* __restrict__ user_emb,
                                const float* __restrict__ item_emb,
                                const float* __restrict__ alpha_w,
                                const float* __restrict__ alpha_b,
                                const int*   __restrict__ edge_index,
                                float* __restrict__ tpw,
                                float* __restrict__ aux) {
    __shared__ int   s_u[32];
    __shared__ float s_ev[32];

    int tid  = threadIdx.x;
    size_t g = (size_t)blockIdx.x * blockDim.x + tid;
    size_t e = g >> 3;
    int sl   = tid & 7;
    int b    = (int)(e / NE);
    int el   = (int)(e - (size_t)b * NE);

    const int* ei = edge_index + (size_t)b * 2 * NE;
    int u = ei[el];
    int i = ei[NE + el];

    const float4* up = (const float4*)&user_emb[(size_t)u * (N_BEH * DIM) + b * DIM + sl * 8];
    const float4* ip = (const float4*)&item_emb[(size_t)i * (N_BEH * DIM) + b * DIM + sl * 8];
    const float4* ap = (const float4*)&alpha_w[b * DIM + sl * 8];
    float4 u0 = up[0], u1 = up[1];
    float4 i0 = ip[0], i1 = ip[1];
    float4 a0 = ap[0], a1 = ap[1];

    float d, z = 0.f, a2 = 0.f;
    d = fabsf(u0.x - i0.x); z += d * a0.x; a2 += d * d;
    d = fabsf(u0.y - i0.y); z += d * a0.y; a2 += d * d;
    d = fabsf(u0.z - i0.z); z += d * a0.z; a2 += d * d;
    d = fabsf(u0.w - i0.w); z += d * a0.w; a2 += d * d;
    d = fabsf(u1.x - i1.x); z += d * a1.x; a2 += d * d;
    d = fabsf(u1.y - i1.y); z += d * a1.y; a2 += d * d;
    d = fabsf(u1.z - i1.z); z += d * a1.z; a2 += d * d;
    d = fabsf(u1.w - i1.w); z += d * a1.w; a2 += d * d;

    #pragma unroll
    for (int o = 4; o; o >>= 1) {
        z  += __shfl_xor_sync(0xffffffffu, z,  o);
        a2 += __shfl_xor_sync(0xffffffffu, a2, o);
    }

    int slot = tid >> 3;
    if (sl == 0) {
        z += alpha_b[b];
        float act = (z > 0.0f) ? z : (expf(z) - 1.0f);
        float ev  = expf(act);
        tpw[(size_t)b * NE + el] = ev;
        aux[(size_t)b * NE + el] = a2;
        s_u[slot]  = u;
        s_ev[slot] = ev;
    }
    __syncthreads();

    if (tid < 32) {
        int myu = s_u[tid];
        bool head = (tid == 0) || (s_u[tid - 1] != myu);
        if (head) {
            float sum = s_ev[tid];
            #pragma unroll 4
            for (int k = tid + 1; k < 32 && s_u[k] == myu; k++) sum += s_ev[k];
            float* dst = &g_S[b * N_USER + myu];
            asm volatile("red.global.add.f32 [%0], %1;" :: "l"(dst), "f"(sum) : "memory");
        }
    }
}

// ---------------------------------------------------------------------------
// Normalize tpw (1 thread per edge) + compact masked edges.
// ---------------------------------------------------------------------------
__global__ void norm_compact_kernel(const int* __restrict__ edge_index,
                                    float* __restrict__ tpw) {
    int idx = blockIdx.x * blockDim.x + threadIdx.x;
    bool valid = idx < NE_ALL;
    int b = 0, e = 0, u = 0, i = 0;
    float w = 0.0f;
    bool m = false;
    if (valid) {
        b = idx / NE;
        e = idx - b * NE;
        const int* ei = edge_index + (size_t)b * 2 * NE;
        u = ei[e];
        i = ei[NE + e];
        w = tpw[idx] / g_S[b * N_USER + u];
        tpw[idx] = w;
        m = (g_mask[i] != 0);
    }
    unsigned ballot = __ballot_sync(0xffffffffu, m);
    int lane = threadIdx.x & 31;
    int cnt  = __popc(ballot);
    int base = 0;
    if (lane == 0 && cnt) base = atomicAdd(&g_cnt, cnt);
    base = __shfl_sync(0xffffffffu, base, 0);
    if (m) {
        int off = base + __popc(ballot & ((1u << lane) - 1u));
        g_cu[off]  = u * (N_BEH * DIM) + b * DIM;
        g_cib[off] = (b * N_ITEM + i) * DIM;
        g_cw[off]  = w;
    }
}

// ---------------------------------------------------------------------------
// Dense scatter over compacted list: 16 lanes per edge, grid-stride.
// ---------------------------------------------------------------------------
__global__ void scatter2_kernel(const float* __restrict__ user_emb) {
    int l    = threadIdx.x & 15;
    int slot = (blockIdx.x * blockDim.x + threadIdx.x) >> 4;
    int stride = (gridDim.x * blockDim.x) >> 4;
    int total = g_cnt;
    for (int e = slot; e < total; e += stride) {
        int uoff = g_cu[e];
        int aoff = g_cib[e];
        float w  = g_cw[e];
        float4 uv = *(const float4*)&user_emb[(size_t)uoff + 4 * l];
        float* dst = &g_A[(size_t)aoff + 4 * l];
        asm volatile("red.global.add.v4.f32 [%0], {%1,%2,%3,%4};"
                     :: "l"(dst), "f"(w * uv.x), "f"(w * uv.y),
                        "f"(w * uv.z), "f"(w * uv.w) : "memory");
    }
}

// ---------------------------------------------------------------------------
// Pass C: attention + LN over 12288 gathered rows (unchanged).
// ---------------------------------------------------------------------------
#define TEAM_F 1216

__global__ void attn_kernel(const float* __restrict__ user_emb,
                            const float* __restrict__ item_emb,
                            const float* __restrict__ wq, const float* __restrict__ bq,
                            const float* __restrict__ wk, const float* __restrict__ bk,
                            const float* __restrict__ wv, const float* __restrict__ bv,
                            const float* __restrict__ wo, const float* __restrict__ bo,
                            const float* __restrict__ lng, const float* __restrict__ lnb,
                            const int* __restrict__ users,
                            const int* __restrict__ pos_items,
                            const int* __restrict__ neg_items,
                            float* __restrict__ emb_out) {
    __shared__ float sm[4 * TEAM_F];
    int team = threadIdx.x >> 6;
    int t    = threadIdx.x & 63;
    int row  = blockIdx.x * 4 + team;

    float* base = sm + team * TEAM_F;
    float* xs = base;
    float* qs = base + 192;
    float* ks = base + 384;
    float* vs = base + 576;
    float* ao = base + 768;
    float* hh = base + 960;
    float* sc = base + 1152;
    float* mus = base + 1188;
    float* rss = base + 1191;

    int node; bool is_user;
    if (row < BATCH)          { node = users[row];                 is_user = true;  }
    else if (row < 2 * BATCH) { node = pos_items[row - BATCH];     is_user = false; }
    else                      { node = neg_items[row - 2 * BATCH]; is_user = false; }

    #pragma unroll
    for (int beh = 0; beh < 3; beh++) {
        float v;
        if (is_user) {
            v = user_emb[(size_t)node * (N_BEH * DIM) + beh * DIM + t];
        } else {
            v = 2.0f * g_A[((size_t)beh * N_ITEM + node) * DIM + t]
                + item_emb[(size_t)node * (N_BEH * DIM) + beh * DIM + t];
        }
        xs[beh * 64 + t] = v;
    }
    __syncthreads();

    {
        float aq0 = bq[t], aq1 = aq0, aq2 = aq0;
        float ak0 = bk[t], ak1 = ak0, ak2 = ak0;
        float av0 = bv[t], av1 = av0, av2 = av0;
        #pragma unroll 8
        for (int d = 0; d < 64; d++) {
            float w1 = wq[d * 64 + t];
            float w2 = wk[d * 64 + t];
            float w3 = wv[d * 64 + t];
            float x0 = xs[d], x1 = xs[64 + d], x2 = xs[128 + d];
            aq0 += x0 * w1; aq1 += x1 * w1; aq2 += x2 * w1;
            ak0 += x0 * w2; ak1 += x1 * w2; ak2 += x2 * w2;
            av0 += x0 * w3; av1 += x1 * w3; av2 += x2 * w3;
        }
        qs[t] = aq0; qs[64 + t] = aq1; qs[128 + t] = aq2;
        ks[t] = ak0; ks[64 + t] = ak1; ks[128 + t] = ak2;
        vs[t] = av0; vs[64 + t] = av1; vs[128 + t] = av2;
    }
    __syncthreads();

    if (t < 36) {
        int h  = t / 9;
        int qb = (t % 9) / 3;
        int kb = t % 3;
        float s = 0.0f;
        #pragma unroll
        for (int j = 0; j < 16; j++)
            s += qs[qb * 64 + h * 16 + j] * ks[kb * 64 + h * 16 + j];
        sc[t] = s * 0.25f;
    }
    __syncthreads();

    if (t < 12) {
        int bidx = t * 3;
        float s0 = sc[bidx], s1 = sc[bidx + 1], s2 = sc[bidx + 2];
        float m = fmaxf(s0, fmaxf(s1, s2));
        float e0 = expf(s0 - m), e1 = expf(s1 - m), e2 = expf(s2 - m);
        float inv = 1.0f / (e0 + e1 + e2);
        sc[bidx] = e0 * inv; sc[bidx + 1] = e1 * inv; sc[bidx + 2] = e2 * inv;
    }
    __syncthreads();

    {
        int h = t >> 4;
        #pragma unroll
        for (int qb = 0; qb < 3; qb++) {
            float a = 0.0f;
            #pragma unroll
            for (int kb = 0; kb < 3; kb++)
                a += sc[h * 9 + qb * 3 + kb] * vs[kb * 64 + t];
            ao[qb * 64 + t] = a;
        }
    }
    __syncthreads();

    {
        float a0 = bo[t], a1 = a0, a2 = a0;
        #pragma unroll 8
        for (int d = 0; d < 64; d++) {
            float w = wo[d * 64 + t];
            a0 += ao[d] * w; a1 += ao[64 + d] * w; a2 += ao[128 + d] * w;
        }
        hh[t]       = a0 + xs[t];
        hh[64 + t]  = a1 + xs[64 + t];
        hh[128 + t] = a2 + xs[128 + t];
    }
    __syncthreads();

    if (t < 3) {
        float s = 0.0f;
        #pragma unroll 8
        for (int j = 0; j < 64; j++) s += hh[t * 64 + j];
        float mu = s * (1.0f / 64.0f);
        float v = 0.0f;
        #pragma unroll 8
        for (int j = 0; j < 64; j++) {
            float d = hh[t * 64 + j] - mu;
            v += d * d;
        }
        v *= (1.0f / 64.0f);
        mus[t] = mu;
        rss[t] = rsqrtf(v + LN_EPS);
    }
    __syncthreads();

    {
        float gg = lng[t], bb = lnb[t];
        float g = 0.0f;
        #pragma unroll
        for (int qb = 0; qb < 3; qb++)
            g += (hh[qb * 64 + t] - mus[qb]) * rss[qb] * gg + bb;
        emb_out[(size_t)row * 64 + t] = g;
    }
}

// ---------------------------------------------------------------------------
extern "C" void kernel_launch(void* const* d_in, const int* in_sizes, int n_in,
                              void* d_out, int out_size) {
    const float* user_emb = (const float*)d_in[0];
    const float* item_emb = (const float*)d_in[1];
    const float* alpha_w  = (const float*)d_in[2];
    const float* alpha_b  = (const float*)d_in[3];
    const float* wq = (const float*)d_in[4];
    const float* bq = (const float*)d_in[5];
    const float* wk = (const float*)d_in[6];
    const float* bk = (const float*)d_in[7];
    const float* wv = (const float*)d_in[8];
    const float* bv = (const float*)d_in[9];
    const float* wo = (const float*)d_in[10];
    const float* bo = (const float*)d_in[11];
    const float* lng = (const float*)d_in[12];
    const float* lnb = (const float*)d_in[13];
    const int* edge_index = (const int*)d_in[14];
    const int* users      = (const int*)d_in[15];
    const int* pos_items  = (const int*)d_in[16];
    const int* neg_items  = (const int*)d_in[17];

    float* out     = (float*)d_out;
    float* emb_out = out;
    float* tpw     = out + (size_t)3 * BATCH * DIM;
    float* aux     = tpw + (size_t)N_BEH * NE;

    zero_small_kernel<<<256, 256>>>();
    mask_kernel<<<(BATCH + 255) / 256, 256>>>(pos_items, neg_items);
    zero_A_masked_kernel<<<(N_BEH * N_ITEM * 16 + 255) / 256, 256>>>();

    edge_act_kernel<<<(size_t)NE_ALL * 8 / 256, 256>>>(user_emb, item_emb,
                                                       alpha_w, alpha_b,
                                                       edge_index, tpw, aux);

    norm_compact_kernel<<<(NE_ALL + 255) / 256, 256>>>(edge_index, tpw);

    scatter2_kernel<<<4096, 256>>>(user_emb);

    attn_kernel<<<(3 * BATCH) / 4, 256>>>(user_emb, item_emb,
                                          wq, bq, wk, bk, wv, bv, wo, bo,
                                          lng, lnb, users, pos_items, neg_items,
                                          emb_out);
}

// round 4
// speedup vs baseline: 1.9808x; 1.0430x over previous
#include <cuda_runtime.h>
#include <math.h>

#define N_USER  100000
#define N_ITEM  50000
#define DIM     64
#define N_BEH   3
#define NE      1000000
#define NE_ALL  (N_BEH * NE)
#define BATCH   4096
#define LN_EPS  1e-5f

// Scratch
__device__ float g_S[N_BEH * N_USER];
__device__ float g_A[(size_t)N_BEH * N_ITEM * DIM];
__device__ int   g_mask[N_ITEM];
__device__ int   g_cnt;
__device__ int   g_cu[NE_ALL];
__device__ int   g_cib[NE_ALL];
__device__ float g_cw[NE_ALL];

// ---------------------------------------------------------------------------
__global__ void zero_small_kernel() {
    int idx = blockIdx.x * blockDim.x + threadIdx.x;
    if (idx == 0) g_cnt = 0;
    for (int i = idx; i < N_BEH * N_USER; i += gridDim.x * blockDim.x)
        g_S[i] = 0.0f;
    for (int i = idx; i < N_ITEM; i += gridDim.x * blockDim.x)
        g_mask[i] = 0;
}

__global__ void mask_kernel(const int* __restrict__ pos_items,
                            const int* __restrict__ neg_items) {
    int t = blockIdx.x * blockDim.x + threadIdx.x;
    if (t < BATCH) {
        g_mask[pos_items[t]] = 1;
        g_mask[neg_items[t]] = 1;
    }
}

__global__ void zero_A_masked_kernel() {
    int idx = blockIdx.x * blockDim.x + threadIdx.x;
    int row = idx >> 4;
    if (row >= N_BEH * N_ITEM) return;
    int i = row % N_ITEM;
    if (g_mask[i]) {
        float4* dst = (float4*)&g_A[(size_t)row * DIM] + (idx & 15);
        *dst = make_float4(0.f, 0.f, 0.f, 0.f);
    }
}

// ---------------------------------------------------------------------------
// Pass A v3: 8 lanes/edge, 4 edges/warp, warp-local segmented S reduction.
// No shared memory, no block barrier.
// ---------------------------------------------------------------------------
__global__ void edge_act_kernel(const float* __restrict__ user_emb,
                                const float* __restrict__ item_emb,
                                const float* __restrict__ alpha_w,
                                const float* __restrict__ alpha_b,
                                const int*   __restrict__ edge_index,
                                float* __restrict__ tpw,
                                float* __restrict__ aux) {
    const unsigned FULL = 0xffffffffu;
    int tid  = threadIdx.x;
    int lane = tid & 31;
    int sl   = lane & 7;               // sub-lane within edge
    size_t e = ((size_t)blockIdx.x * blockDim.x + tid) >> 3;
    int b    = (int)(e / NE);          // uniform per warp (NE % 4 == 0)
    int el   = (int)(e - (size_t)b * NE);

    const int* ei = edge_index + (size_t)b * 2 * NE;
    int u = ei[el];
    int i = ei[NE + el];

    const float4* up = (const float4*)&user_emb[(size_t)u * (N_BEH * DIM) + b * DIM + sl * 8];
    const float4* ip = (const float4*)&item_emb[(size_t)i * (N_BEH * DIM) + b * DIM + sl * 8];
    const float4* ap = (const float4*)&alpha_w[b * DIM + sl * 8];
    float4 u0 = up[0], u1 = up[1];
    float4 i0 = ip[0], i1 = ip[1];
    float4 a0 = ap[0], a1 = ap[1];

    float d, z = 0.f, a2 = 0.f;
    d = fabsf(u0.x - i0.x); z += d * a0.x; a2 += d * d;
    d = fabsf(u0.y - i0.y); z += d * a0.y; a2 += d * d;
    d = fabsf(u0.z - i0.z); z += d * a0.z; a2 += d * d;
    d = fabsf(u0.w - i0.w); z += d * a0.w; a2 += d * d;
    d = fabsf(u1.x - i1.x); z += d * a1.x; a2 += d * d;
    d = fabsf(u1.y - i1.y); z += d * a1.y; a2 += d * d;
    d = fabsf(u1.z - i1.z); z += d * a1.z; a2 += d * d;
    d = fabsf(u1.w - i1.w); z += d * a1.w; a2 += d * d;

    #pragma unroll
    for (int o = 4; o; o >>= 1) {
        z  += __shfl_xor_sync(FULL, z,  o);
        a2 += __shfl_xor_sync(FULL, a2, o);
    }

    // every lane computes ev (avoids divergence); lane sl==0 stores
    z += alpha_b[b];
    float act = (z > 0.0f) ? z : (expf(z) - 1.0f);
    float ev  = expf(act);
    if (sl == 0) {
        tpw[(size_t)b * NE + el] = ev;
        aux[(size_t)b * NE + el] = a2;
    }

    // warp-local segmented reduction of ev over the 4 edge slots
    int   us0 = __shfl_sync(FULL, u, 0);
    int   us1 = __shfl_sync(FULL, u, 8);
    int   us2 = __shfl_sync(FULL, u, 16);
    int   us3 = __shfl_sync(FULL, u, 24);
    float vs0 = __shfl_sync(FULL, ev, 0);
    float vs1 = __shfl_sync(FULL, ev, 8);
    float vs2 = __shfl_sync(FULL, ev, 16);
    float vs3 = __shfl_sync(FULL, ev, 24);

    if (lane == 0) {
        int   us[4] = {us0, us1, us2, us3};
        float vv[4] = {vs0, vs1, vs2, vs3};
        int k = 0;
        while (k < 4) {
            int uu = us[k];
            float s = vv[k];
            int j = k + 1;
            while (j < 4 && us[j] == uu) { s += vv[j]; j++; }
            float* dst = &g_S[b * N_USER + uu];
            asm volatile("red.global.add.f32 [%0], %1;" :: "l"(dst), "f"(s) : "memory");
            k = j;
        }
    }
}

// ---------------------------------------------------------------------------
// Normalize tpw + compact masked edges.
// ---------------------------------------------------------------------------
__global__ void norm_compact_kernel(const int* __restrict__ edge_index,
                                    float* __restrict__ tpw) {
    int idx = blockIdx.x * blockDim.x + threadIdx.x;
    bool valid = idx < NE_ALL;
    int b = 0, e = 0, u = 0, i = 0;
    float w = 0.0f;
    bool m = false;
    if (valid) {
        b = idx / NE;
        e = idx - b * NE;
        const int* ei = edge_index + (size_t)b * 2 * NE;
        u = ei[e];
        i = ei[NE + e];
        w = tpw[idx] / g_S[b * N_USER + u];
        tpw[idx] = w;
        m = (g_mask[i] != 0);
    }
    unsigned ballot = __ballot_sync(0xffffffffu, m);
    int lane = threadIdx.x & 31;
    int cnt  = __popc(ballot);
    int base = 0;
    if (lane == 0 && cnt) base = atomicAdd(&g_cnt, cnt);
    base = __shfl_sync(0xffffffffu, base, 0);
    if (m) {
        int off = base + __popc(ballot & ((1u << lane) - 1u));
        g_cu[off]  = u * (N_BEH * DIM) + b * DIM;
        g_cib[off] = (b * N_ITEM + i) * DIM;
        g_cw[off]  = w;
    }
}

// ---------------------------------------------------------------------------
// Dense scatter over compacted list.
// ---------------------------------------------------------------------------
__global__ void scatter2_kernel(const float* __restrict__ user_emb) {
    int l    = threadIdx.x & 15;
    int slot = (blockIdx.x * blockDim.x + threadIdx.x) >> 4;
    int stride = (gridDim.x * blockDim.x) >> 4;
    int total = g_cnt;
    for (int e = slot; e < total; e += stride) {
        int uoff = g_cu[e];
        int aoff = g_cib[e];
        float w  = g_cw[e];
        float4 uv = *(const float4*)&user_emb[(size_t)uoff + 4 * l];
        float* dst = &g_A[(size_t)aoff + 4 * l];
        asm volatile("red.global.add.v4.f32 [%0], {%1,%2,%3,%4};"
                     :: "l"(dst), "f"(w * uv.x), "f"(w * uv.y),
                        "f"(w * uv.z), "f"(w * uv.w) : "memory");
    }
}

// ---------------------------------------------------------------------------
// Pass C v2: 8 rows/block, 128 threads, 4 rows/thread in matmul phases.
// smem aliasing: ao == qs region, hh == ks region.
// ---------------------------------------------------------------------------
#define ROWS_PB 8
#define ROW_F   816
// layout per row: xs@0, qs@192(=ao), ks@384(=hh), vs@576, sc@768, mus@804, rss@808

__global__ __launch_bounds__(128)
void attn_kernel(const float* __restrict__ user_emb,
                 const float* __restrict__ item_emb,
                 const float* __restrict__ wq, const float* __restrict__ bq,
                 const float* __restrict__ wk, const float* __restrict__ bk,
                 const float* __restrict__ wv, const float* __restrict__ bv,
                 const float* __restrict__ wo, const float* __restrict__ bo,
                 const float* __restrict__ lng, const float* __restrict__ lnb,
                 const int* __restrict__ users,
                 const int* __restrict__ pos_items,
                 const int* __restrict__ neg_items,
                 float* __restrict__ emb_out) {
    __shared__ float sm[ROWS_PB * ROW_F];   // 26.1 KB
    int t = threadIdx.x & 63;
    int g = threadIdx.x >> 6;               // 0..1
    int row0 = blockIdx.x * ROWS_PB;

    // ---- load x for my 4 rows ----
    #pragma unroll
    for (int r = 0; r < 4; r++) {
        int lr  = g * 4 + r;
        int row = row0 + lr;
        int node; bool is_user;
        if (row < BATCH)          { node = users[row];                 is_user = true;  }
        else if (row < 2 * BATCH) { node = pos_items[row - BATCH];     is_user = false; }
        else                      { node = neg_items[row - 2 * BATCH]; is_user = false; }
        float* xs = sm + lr * ROW_F;
        #pragma unroll
        for (int beh = 0; beh < 3; beh++) {
            float v;
            if (is_user) {
                v = user_emb[(size_t)node * (N_BEH * DIM) + beh * DIM + t];
            } else {
                v = 2.0f * g_A[((size_t)beh * N_ITEM + node) * DIM + t]
                    + item_emb[(size_t)node * (N_BEH * DIM) + beh * DIM + t];
            }
            xs[beh * 64 + t] = v;
        }
    }
    __syncthreads();

    // ---- qkv: thread owns column t for 4 rows x 3 behaviors ----
    {
        float aq[4][3], ak[4][3], av[4][3];
        float bqv = bq[t], bkv = bk[t], bvv = bv[t];
        #pragma unroll
        for (int r = 0; r < 4; r++)
            #pragma unroll
            for (int beh = 0; beh < 3; beh++) {
                aq[r][beh] = bqv; ak[r][beh] = bkv; av[r][beh] = bvv;
            }
        #pragma unroll 4
        for (int d4 = 0; d4 < 64; d4 += 4) {
            float w1[4], w2[4], w3[4];
            #pragma unroll
            for (int k = 0; k < 4; k++) {
                w1[k] = wq[(d4 + k) * 64 + t];
                w2[k] = wk[(d4 + k) * 64 + t];
                w3[k] = wv[(d4 + k) * 64 + t];
            }
            #pragma unroll
            for (int r = 0; r < 4; r++) {
                const float* xr = sm + (g * 4 + r) * ROW_F;
                #pragma unroll
                for (int beh = 0; beh < 3; beh++) {
                    float4 x = *(const float4*)&xr[beh * 64 + d4];
                    aq[r][beh] += x.x * w1[0] + x.y * w1[1] + x.z * w1[2] + x.w * w1[3];
                    ak[r][beh] += x.x * w2[0] + x.y * w2[1] + x.z * w2[2] + x.w * w2[3];
                    av[r][beh] += x.x * w3[0] + x.y * w3[1] + x.z * w3[2] + x.w * w3[3];
                }
            }
        }
        #pragma unroll
        for (int r = 0; r < 4; r++) {
            float* base = sm + (g * 4 + r) * ROW_F;
            #pragma unroll
            for (int beh = 0; beh < 3; beh++) {
                base[192 + beh * 64 + t] = aq[r][beh];   // qs
                base[384 + beh * 64 + t] = ak[r][beh];   // ks
                base[576 + beh * 64 + t] = av[r][beh];   // vs
            }
        }
    }
    __syncthreads();

    // ---- scores: 8 rows x 36 = 288 units over 128 threads ----
    for (int uu = threadIdx.x; uu < ROWS_PB * 36; uu += 128) {
        int lr  = uu / 36;
        int rem = uu - lr * 36;
        int h   = rem / 9;
        int qb  = (rem % 9) / 3;
        int kb  = rem % 3;
        float* base = sm + lr * ROW_F;
        float s = 0.0f;
        #pragma unroll
        for (int j = 0; j < 16; j++)
            s += base[192 + qb * 64 + h * 16 + j] * base[384 + kb * 64 + h * 16 + j];
        base[768 + rem] = s * 0.25f;
    }
    __syncthreads();

    // ---- softmax: 8 rows x 12 = 96 units ----
    if (threadIdx.x < ROWS_PB * 12) {
        int lr = threadIdx.x / 12;
        int p  = threadIdx.x - lr * 12;
        float* sc = sm + lr * ROW_F + 768 + p * 3;
        float s0 = sc[0], s1 = sc[1], s2 = sc[2];
        float m = fmaxf(s0, fmaxf(s1, s2));
        float e0 = expf(s0 - m), e1 = expf(s1 - m), e2 = expf(s2 - m);
        float inv = 1.0f / (e0 + e1 + e2);
        sc[0] = e0 * inv; sc[1] = e1 * inv; sc[2] = e2 * inv;
    }
    __syncthreads();

    // ---- att_out -> ao (aliases qs): 8 rows x 64 = 512 units ----
    for (int uu = threadIdx.x; uu < ROWS_PB * 64; uu += 128) {
        int lr = uu >> 6;
        int tt = uu & 63;
        int h  = tt >> 4;
        float* base = sm + lr * ROW_F;
        #pragma unroll
        for (int qb = 0; qb < 3; qb++) {
            float a = 0.0f;
            #pragma unroll
            for (int kb = 0; kb < 3; kb++)
                a += base[768 + h * 9 + qb * 3 + kb] * base[576 + kb * 64 + tt];
            base[192 + qb * 64 + tt] = a;   // ao
        }
    }
    __syncthreads();

    // ---- out-proj + residual -> hh (aliases ks) ----
    {
        float acc[4][3];
        float bov = bo[t];
        #pragma unroll
        for (int r = 0; r < 4; r++)
            #pragma unroll
            for (int beh = 0; beh < 3; beh++) acc[r][beh] = bov;
        #pragma unroll 4
        for (int d4 = 0; d4 < 64; d4 += 4) {
            float w[4];
            #pragma unroll
            for (int k = 0; k < 4; k++) w[k] = wo[(d4 + k) * 64 + t];
            #pragma unroll
            for (int r = 0; r < 4; r++) {
                const float* base = sm + (g * 4 + r) * ROW_F;
                #pragma unroll
                for (int beh = 0; beh < 3; beh++) {
                    float4 a = *(const float4*)&base[192 + beh * 64 + d4];
                    acc[r][beh] += a.x * w[0] + a.y * w[1] + a.z * w[2] + a.w * w[3];
                }
            }
        }
        __syncthreads();   // ao reads done before hh overwrites ks? (hh != ao, but keep order safe)
        #pragma unroll
        for (int r = 0; r < 4; r++) {
            float* base = sm + (g * 4 + r) * ROW_F;
            #pragma unroll
            for (int beh = 0; beh < 3; beh++)
                base[384 + beh * 64 + t] = acc[r][beh] + base[beh * 64 + t];  // hh
        }
    }
    __syncthreads();

    // ---- LN stats: 8 rows x 3 beh = 24 units ----
    if (threadIdx.x < ROWS_PB * 3) {
        int lr  = threadIdx.x / 3;
        int beh = threadIdx.x - lr * 3;
        float* hh = sm + lr * ROW_F + 384 + beh * 64;
        float s = 0.0f;
        #pragma unroll 8
        for (int j = 0; j < 64; j++) s += hh[j];
        float mu = s * (1.0f / 64.0f);
        float v = 0.0f;
        #pragma unroll 8
        for (int j = 0; j < 64; j++) {
            float dd = hh[j] - mu;
            v += dd * dd;
        }
        v *= (1.0f / 64.0f);
        sm[lr * ROW_F + 804 + beh] = mu;
        sm[lr * ROW_F + 808 + beh] = rsqrtf(v + LN_EPS);
    }
    __syncthreads();

    // ---- normalize + sum over behaviors ----
    for (int uu = threadIdx.x; uu < ROWS_PB * 64; uu += 128) {
        int lr = uu >> 6;
        int tt = uu & 63;
        float* base = sm + lr * ROW_F;
        float gg = lng[tt], bb = lnb[tt];
        float gsum = 0.0f;
        #pragma unroll
        for (int beh = 0; beh < 3; beh++)
            gsum += (base[384 + beh * 64 + tt] - base[804 + beh]) * base[808 + beh] * gg + bb;
        emb_out[(size_t)(row0 + lr) * 64 + tt] = gsum;
    }
}

// ---------------------------------------------------------------------------
extern "C" void kernel_launch(void* const* d_in, const int* in_sizes, int n_in,
                              void* d_out, int out_size) {
    const float* user_emb = (const float*)d_in[0];
    const float* item_emb = (const float*)d_in[1];
    const float* alpha_w  = (const float*)d_in[2];
    const float* alpha_b  = (const float*)d_in[3];
    const float* wq = (const float*)d_in[4];
    const float* bq = (const float*)d_in[5];
    const float* wk = (const float*)d_in[6];
    const float* bk = (const float*)d_in[7];
    const float* wv = (const float*)d_in[8];
    const float* bv = (const float*)d_in[9];
    const float* wo = (const float*)d_in[10];
    const float* bo = (const float*)d_in[11];
    const float* lng = (const float*)d_in[12];
    const float* lnb = (const float*)d_in[13];
    const int* edge_index = (const int*)d_in[14];
    const int* users      = (const int*)d_in[15];
    const int* pos_items  = (const int*)d_in[16];
    const int* neg_items  = (const int*)d_in[17];

    float* out     = (float*)d_out;
    float* emb_out = out;
    float* tpw     = out + (size_t)3 * BATCH * DIM;
    float* aux     = tpw + (size_t)N_BEH * NE;

    zero_small_kernel<<<256, 256>>>();
    mask_kernel<<<(BATCH + 255) / 256, 256>>>(pos_items, neg_items);
    zero_A_masked_kernel<<<(N_BEH * N_ITEM * 16 + 255) / 256, 256>>>();

    edge_act_kernel<<<(size_t)NE_ALL * 8 / 256, 256>>>(user_emb, item_emb,
                                                       alpha_w, alpha_b,
                                                       edge_index, tpw, aux);

    norm_compact_kernel<<<(NE_ALL + 255) / 256, 256>>>(edge_index, tpw);

    scatter2_kernel<<<4096, 256>>>(user_emb);

    attn_kernel<<<(3 * BATCH) / ROWS_PB, 128>>>(user_emb, item_emb,
                                                wq, bq, wk, bk, wv, bv, wo, bo,
                                                lng, lnb, users, pos_items, neg_items,
                                                emb_out);
}

// round 6
// speedup vs baseline: 2.7974x; 1.4123x over previous
#include <cuda_runtime.h>
#include <math.h>

#define N_USER  100000
#define N_ITEM  50000
#define DIM     64
#define N_BEH   3
#define NE      1000000
#define NE_ALL  (N_BEH * NE)
#define BATCH   4096
#define LN_EPS  1e-5f

// Scratch
__device__ float g_S[N_BEH * N_USER];
__device__ float g_A[(size_t)N_BEH * N_ITEM * DIM];
__device__ int   g_mask[N_ITEM];
__device__ int   g_cnt;
__device__ int   g_cu[NE_ALL];
__device__ int   g_cib[NE_ALL];
__device__ float g_cw[NE_ALL];

// ---------------------------------------------------------------------------
__global__ void zero_small_kernel() {
    int idx = blockIdx.x * blockDim.x + threadIdx.x;
    if (idx == 0) g_cnt = 0;
    for (int i = idx; i < N_BEH * N_USER; i += gridDim.x * blockDim.x)
        g_S[i] = 0.0f;
    for (int i = idx; i < N_ITEM; i += gridDim.x * blockDim.x)
        g_mask[i] = 0;
}

__global__ void mask_kernel(const int* __restrict__ pos_items,
                            const int* __restrict__ neg_items) {
    int t = blockIdx.x * blockDim.x + threadIdx.x;
    if (t < BATCH) {
        g_mask[pos_items[t]] = 1;
        g_mask[neg_items[t]] = 1;
    }
}

__global__ void zero_A_masked_kernel() {
    int idx = blockIdx.x * blockDim.x + threadIdx.x;
    int row = idx >> 4;
    if (row >= N_BEH * N_ITEM) return;
    int i = row % N_ITEM;
    if (g_mask[i]) {
        float4* dst = (float4*)&g_A[(size_t)row * DIM] + (idx & 15);
        *dst = make_float4(0.f, 0.f, 0.f, 0.f);
    }
}

// ---------------------------------------------------------------------------
// 256-bit load helper (sm_100a): 8 consecutive floats, 32B-aligned.
// ---------------------------------------------------------------------------
__device__ __forceinline__ void ldg_v8(const float* p, float* r) {
    asm volatile("ld.global.v8.f32 {%0,%1,%2,%3,%4,%5,%6,%7}, [%8];"
                 : "=f"(r[0]), "=f"(r[1]), "=f"(r[2]), "=f"(r[3]),
                   "=f"(r[4]), "=f"(r[5]), "=f"(r[6]), "=f"(r[7])
                 : "l"(p));
}

// ---------------------------------------------------------------------------
// Pass A v5: 4 lanes/edge, 8 edges/warp, v8 (256-bit) loads.
//   ev = exp(elu(|ue-ie|.alpha_w + alpha_b)), aux = sum(diff^2)
//   direct per-slot red.add of ev into g_S.
// Grid is exact: NE_ALL*4/256 = 46875 blocks.
// ---------------------------------------------------------------------------
__global__ void edge_act_kernel(const float* __restrict__ user_emb,
                                const float* __restrict__ item_emb,
                                const float* __restrict__ alpha_w,
                                const float* __restrict__ alpha_b,
                                const int*   __restrict__ edge_index,
                                float* __restrict__ tpw,
                                float* __restrict__ aux) {
    const unsigned FULL = 0xffffffffu;
    int tid  = threadIdx.x;
    int lane = tid & 31;
    int sl   = lane & 3;                 // sub-lane within edge (0..3)
    size_t e = ((size_t)blockIdx.x * blockDim.x + tid) >> 2;   // edge id
    int b    = (int)(e / NE);            // uniform per warp
    int el   = (int)(e - (size_t)b * NE);

    const int* ei = edge_index + (size_t)b * 2 * NE;
    int u = ei[el];
    int i = ei[NE + el];

    // each lane covers 64B = 16 floats: dims [sl*16, sl*16+16)
    const float* up = &user_emb[(size_t)u * (N_BEH * DIM) + b * DIM + sl * 16];
    const float* ip = &item_emb[(size_t)i * (N_BEH * DIM) + b * DIM + sl * 16];
    const float* ap = &alpha_w[b * DIM + sl * 16];

    float uv[16], iv[16], av[16];
    ldg_v8(up,     uv);
    ldg_v8(ip,     iv);
    ldg_v8(ap,     av);
    ldg_v8(up + 8, uv + 8);
    ldg_v8(ip + 8, iv + 8);
    ldg_v8(ap + 8, av + 8);

    float z = 0.f, a2 = 0.f;
    #pragma unroll
    for (int k = 0; k < 16; k++) {
        float d = fabsf(uv[k] - iv[k]);
        z  += d * av[k];
        a2 += d * d;
    }

    #pragma unroll
    for (int o = 2; o; o >>= 1) {
        z  += __shfl_xor_sync(FULL, z,  o);
        a2 += __shfl_xor_sync(FULL, a2, o);
    }

    z += alpha_b[b];
    float act = (z > 0.0f) ? z : (expf(z) - 1.0f);   // elu(alpha=1)
    float ev  = expf(act);                           // bounded; no max shift
    if (sl == 0) {
        tpw[(size_t)b * NE + el] = ev;
        aux[(size_t)b * NE + el] = a2;
        float* dst = &g_S[b * N_USER + u];
        asm volatile("red.global.add.f32 [%0], %1;" :: "l"(dst), "f"(ev) : "memory");
    }
}

// ---------------------------------------------------------------------------
// Normalize tpw (4 edges/thread, vectorized) + compact masked edges.
// TAIL-GUARDED: threads with idx >= NE_ALL contribute cnt=0 but still
// participate in all warp shuffles.
// ---------------------------------------------------------------------------
__global__ void norm_compact_kernel(const int* __restrict__ edge_index,
                                    float* __restrict__ tpw) {
    const unsigned FULL = 0xffffffffu;
    int t4 = blockIdx.x * blockDim.x + threadIdx.x;   // over NE_ALL/4
    int idx = t4 * 4;
    bool valid = (idx < NE_ALL);

    int b = 0, e = 0;
    int4 uu = make_int4(0, 0, 0, 0), ii = make_int4(0, 0, 0, 0);
    float4 w = make_float4(0.f, 0.f, 0.f, 0.f);
    int m0 = 0, m1 = 0, m2 = 0, m3 = 0;

    if (valid) {
        b = idx / NE;                                 // NE % 4 == 0
        e = idx - b * NE;
        const int* ei = edge_index + (size_t)b * 2 * NE;
        uu = *(const int4*)&ei[e];
        ii = *(const int4*)&ei[NE + e];
        float4 tv = *(const float4*)&tpw[idx];
        const float* Sb = &g_S[b * N_USER];
        w.x = tv.x / Sb[uu.x];
        w.y = tv.y / Sb[uu.y];
        w.z = tv.z / Sb[uu.z];
        w.w = tv.w / Sb[uu.w];
        *(float4*)&tpw[idx] = w;
        m0 = g_mask[ii.x]; m1 = g_mask[ii.y]; m2 = g_mask[ii.z]; m3 = g_mask[ii.w];
    }
    int cnt = m0 + m1 + m2 + m3;

    // warp-exclusive scan of cnt
    int lane = threadIdx.x & 31;
    int pre = cnt;
    #pragma unroll
    for (int o = 1; o < 32; o <<= 1) {
        int v = __shfl_up_sync(FULL, pre, o);
        if (lane >= o) pre += v;
    }
    int total = __shfl_sync(FULL, pre, 31);
    int excl  = pre - cnt;
    int base = 0;
    if (lane == 31 && total) base = atomicAdd(&g_cnt, total);
    base = __shfl_sync(FULL, base, 31);

    if (valid && cnt) {
        int off = base + excl;
        int us[4] = {uu.x, uu.y, uu.z, uu.w};
        int is[4] = {ii.x, ii.y, ii.z, ii.w};
        float ws[4] = {w.x, w.y, w.z, w.w};
        int ms[4] = {m0, m1, m2, m3};
        #pragma unroll
        for (int j = 0; j < 4; j++) {
            if (ms[j]) {
                g_cu[off]  = us[j] * (N_BEH * DIM) + b * DIM;
                g_cib[off] = (b * N_ITEM + is[j]) * DIM;
                g_cw[off]  = ws[j];
                off++;
            }
        }
    }
}

// ---------------------------------------------------------------------------
// Dense scatter over compacted list.
// ---------------------------------------------------------------------------
__global__ void scatter2_kernel(const float* __restrict__ user_emb) {
    int l    = threadIdx.x & 15;
    int slot = (blockIdx.x * blockDim.x + threadIdx.x) >> 4;
    int stride = (gridDim.x * blockDim.x) >> 4;
    int total = g_cnt;
    for (int e = slot; e < total; e += stride) {
        int uoff = g_cu[e];
        int aoff = g_cib[e];
        float w  = g_cw[e];
        float4 uv = *(const float4*)&user_emb[(size_t)uoff + 4 * l];
        float* dst = &g_A[(size_t)aoff + 4 * l];
        asm volatile("red.global.add.v4.f32 [%0], {%1,%2,%3,%4};"
                     :: "l"(dst), "f"(w * uv.x), "f"(w * uv.y),
                        "f"(w * uv.z), "f"(w * uv.w) : "memory");
    }
}

// ---------------------------------------------------------------------------
// Pass C: 8 rows/block, 128 threads, 4 rows/thread in matmul phases.
// ---------------------------------------------------------------------------
#define ROWS_PB 8
#define ROW_F   816
// layout per row: xs@0, qs@192(=ao), ks@384(=hh), vs@576, sc@768, mus@804, rss@808

__global__ __launch_bounds__(128)
void attn_kernel(const float* __restrict__ user_emb,
                 const float* __restrict__ item_emb,
                 const float* __restrict__ wq, const float* __restrict__ bq,
                 const float* __restrict__ wk, const float* __restrict__ bk,
                 const float* __restrict__ wv, const float* __restrict__ bv,
                 const float* __restrict__ wo, const float* __restrict__ bo,
                 const float* __restrict__ lng, const float* __restrict__ lnb,
                 const int* __restrict__ users,
                 const int* __restrict__ pos_items,
                 const int* __restrict__ neg_items,
                 float* __restrict__ emb_out) {
    __shared__ float sm[ROWS_PB * ROW_F];
    int t = threadIdx.x & 63;
    int g = threadIdx.x >> 6;
    int row0 = blockIdx.x * ROWS_PB;

    #pragma unroll
    for (int r = 0; r < 4; r++) {
        int lr  = g * 4 + r;
        int row = row0 + lr;
        int node; bool is_user;
        if (row < BATCH)          { node = users[row];                 is_user = true;  }
        else if (row < 2 * BATCH) { node = pos_items[row - BATCH];     is_user = false; }
        else                      { node = neg_items[row - 2 * BATCH]; is_user = false; }
        float* xs = sm + lr * ROW_F;
        #pragma unroll
        for (int beh = 0; beh < 3; beh++) {
            float v;
            if (is_user) {
                v = user_emb[(size_t)node * (N_BEH * DIM) + beh * DIM + t];
            } else {
                v = 2.0f * g_A[((size_t)beh * N_ITEM + node) * DIM + t]
                    + item_emb[(size_t)node * (N_BEH * DIM) + beh * DIM + t];
            }
            xs[beh * 64 + t] = v;
        }
    }
    __syncthreads();

    {
        float aq[4][3], ak[4][3], av[4][3];
        float bqv = bq[t], bkv = bk[t], bvv = bv[t];
        #pragma unroll
        for (int r = 0; r < 4; r++)
            #pragma unroll
            for (int beh = 0; beh < 3; beh++) {
                aq[r][beh] = bqv; ak[r][beh] = bkv; av[r][beh] = bvv;
            }
        #pragma unroll 4
        for (int d4 = 0; d4 < 64; d4 += 4) {
            float w1[4], w2[4], w3[4];
            #pragma unroll
            for (int k = 0; k < 4; k++) {
                w1[k] = wq[(d4 + k) * 64 + t];
                w2[k] = wk[(d4 + k) * 64 + t];
                w3[k] = wv[(d4 + k) * 64 + t];
            }
            #pragma unroll
            for (int r = 0; r < 4; r++) {
                const float* xr = sm + (g * 4 + r) * ROW_F;
                #pragma unroll
                for (int beh = 0; beh < 3; beh++) {
                    float4 x = *(const float4*)&xr[beh * 64 + d4];
                    aq[r][beh] += x.x * w1[0] + x.y * w1[1] + x.z * w1[2] + x.w * w1[3];
                    ak[r][beh] += x.x * w2[0] + x.y * w2[1] + x.z * w2[2] + x.w * w2[3];
                    av[r][beh] += x.x * w3[0] + x.y * w3[1] + x.z * w3[2] + x.w * w3[3];
                }
            }
        }
        #pragma unroll
        for (int r = 0; r < 4; r++) {
            float* base = sm + (g * 4 + r) * ROW_F;
            #pragma unroll
            for (int beh = 0; beh < 3; beh++) {
                base[192 + beh * 64 + t] = aq[r][beh];
                base[384 + beh * 64 + t] = ak[r][beh];
                base[576 + beh * 64 + t] = av[r][beh];
            }
        }
    }
    __syncthreads();

    for (int uu = threadIdx.x; uu < ROWS_PB * 36; uu += 128) {
        int lr  = uu / 36;
        int rem = uu - lr * 36;
        int h   = rem / 9;
        int qb  = (rem % 9) / 3;
        int kb  = rem % 3;
        float* base = sm + lr * ROW_F;
        float s = 0.0f;
        #pragma unroll
        for (int j = 0; j < 16; j++)
            s += base[192 + qb * 64 + h * 16 + j] * base[384 + kb * 64 + h * 16 + j];
        base[768 + rem] = s * 0.25f;
    }
    __syncthreads();

    if (threadIdx.x < ROWS_PB * 12) {
        int lr = threadIdx.x / 12;
        int p  = threadIdx.x - lr * 12;
        float* sc = sm + lr * ROW_F + 768 + p * 3;
        float s0 = sc[0], s1 = sc[1], s2 = sc[2];
        float m = fmaxf(s0, fmaxf(s1, s2));
        float e0 = expf(s0 - m), e1 = expf(s1 - m), e2 = expf(s2 - m);
        float inv = 1.0f / (e0 + e1 + e2);
        sc[0] = e0 * inv; sc[1] = e1 * inv; sc[2] = e2 * inv;
    }
    __syncthreads();

    for (int uu = threadIdx.x; uu < ROWS_PB * 64; uu += 128) {
        int lr = uu >> 6;
        int tt = uu & 63;
        int h  = tt >> 4;
        float* base = sm + lr * ROW_F;
        #pragma unroll
        for (int qb = 0; qb < 3; qb++) {
            float a = 0.0f;
            #pragma unroll
            for (int kb = 0; kb < 3; kb++)
                a += base[768 + h * 9 + qb * 3 + kb] * base[576 + kb * 64 + tt];
            base[192 + qb * 64 + tt] = a;
        }
    }
    __syncthreads();

    {
        float acc[4][3];
        float bov = bo[t];
        #pragma unroll
        for (int r = 0; r < 4; r++)
            #pragma unroll
            for (int beh = 0; beh < 3; beh++) acc[r][beh] = bov;
        #pragma unroll 4
        for (int d4 = 0; d4 < 64; d4 += 4) {
            float w[4];
            #pragma unroll
            for (int k = 0; k < 4; k++) w[k] = wo[(d4 + k) * 64 + t];
            #pragma unroll
            for (int r = 0; r < 4; r++) {
                const float* base = sm + (g * 4 + r) * ROW_F;
                #pragma unroll
                for (int beh = 0; beh < 3; beh++) {
                    float4 a = *(const float4*)&base[192 + beh * 64 + d4];
                    acc[r][beh] += a.x * w[0] + a.y * w[1] + a.z * w[2] + a.w * w[3];
                }
            }
        }
        __syncthreads();
        #pragma unroll
        for (int r = 0; r < 4; r++) {
            float* base = sm + (g * 4 + r) * ROW_F;
            #pragma unroll
            for (int beh = 0; beh < 3; beh++)
                base[384 + beh * 64 + t] = acc[r][beh] + base[beh * 64 + t];
        }
    }
    __syncthreads();

    if (threadIdx.x < ROWS_PB * 3) {
        int lr  = threadIdx.x / 3;
        int beh = threadIdx.x - lr * 3;
        float* hh = sm + lr * ROW_F + 384 + beh * 64;
        float s = 0.0f;
        #pragma unroll 8
        for (int j = 0; j < 64; j++) s += hh[j];
        float mu = s * (1.0f / 64.0f);
        float v = 0.0f;
        #pragma unroll 8
        for (int j = 0; j < 64; j++) {
            float dd = hh[j] - mu;
            v += dd * dd;
        }
        v *= (1.0f / 64.0f);
        sm[lr * ROW_F + 804 + beh] = mu;
        sm[lr * ROW_F + 808 + beh] = rsqrtf(v + LN_EPS);
    }
    __syncthreads();

    for (int uu = threadIdx.x; uu < ROWS_PB * 64; uu += 128) {
        int lr = uu >> 6;
        int tt = uu & 63;
        float* base = sm + lr * ROW_F;
        float gg = lng[tt], bb = lnb[tt];
        float gsum = 0.0f;
        #pragma unroll
        for (int beh = 0; beh < 3; beh++)
            gsum += (base[384 + beh * 64 + tt] - base[804 + beh]) * base[808 + beh] * gg + bb;
        emb_out[(size_t)(row0 + lr) * 64 + tt] = gsum;
    }
}

// ---------------------------------------------------------------------------
extern "C" void kernel_launch(void* const* d_in, const int* in_sizes, int n_in,
                              void* d_out, int out_size) {
    const float* user_emb = (const float*)d_in[0];
    const float* item_emb = (const float*)d_in[1];
    const float* alpha_w  = (const float*)d_in[2];
    const float* alpha_b  = (const float*)d_in[3];
    const float* wq = (const float*)d_in[4];
    const float* bq = (const float*)d_in[5];
    const float* wk = (const float*)d_in[6];
    const float* bk = (const float*)d_in[7];
    const float* wv = (const float*)d_in[8];
    const float* bv = (const float*)d_in[9];
    const float* wo = (const float*)d_in[10];
    const float* bo = (const float*)d_in[11];
    const float* lng = (const float*)d_in[12];
    const float* lnb = (const float*)d_in[13];
    const int* edge_index = (const int*)d_in[14];
    const int* users      = (const int*)d_in[15];
    const int* pos_items  = (const int*)d_in[16];
    const int* neg_items  = (const int*)d_in[17];

    float* out     = (float*)d_out;
    float* emb_out = out;
    float* tpw     = out + (size_t)3 * BATCH * DIM;
    float* aux     = tpw + (size_t)N_BEH * NE;

    zero_small_kernel<<<256, 256>>>();
    mask_kernel<<<(BATCH + 255) / 256, 256>>>(pos_items, neg_items);
    zero_A_masked_kernel<<<(N_BEH * N_ITEM * 16 + 255) / 256, 256>>>();

    // Pass A: 3M edges * 4 lanes / 256 (exact)
    edge_act_kernel<<<(size_t)NE_ALL * 4 / 256, 256>>>(user_emb, item_emb,
                                                       alpha_w, alpha_b,
                                                       edge_index, tpw, aux);

    norm_compact_kernel<<<(NE_ALL / 4 + 255) / 256, 256>>>(edge_index, tpw);

    scatter2_kernel<<<4096, 256>>>(user_emb);

    attn_kernel<<<(3 * BATCH) / ROWS_PB, 128>>>(user_emb, item_emb,
                                                wq, bq, wk, bk, wv, bv, wo, bo,
                                                lng, lnb, users, pos_items, neg_items,
                                                emb_out);
}

// round 8
// speedup vs baseline: 3.2858x; 1.1746x over previous
#include <cuda_runtime.h>
#include <math.h>

#define N_USER  100000
#define N_ITEM  50000
#define DIM     64
#define N_BEH   3
#define NE      1000000
#define NE_ALL  (N_BEH * NE)
#define BATCH   4096
#define LN_EPS  1e-5f

// Scratch
__device__ float g_S[N_BEH * N_USER];
__device__ float g_A[(size_t)N_BEH * N_ITEM * DIM];
__device__ int   g_mask[N_ITEM];
__device__ int   g_cnt;
__device__ int   g_cu[NE_ALL];
__device__ int   g_cib[NE_ALL];
__device__ float g_cw[NE_ALL];

// ---------------------------------------------------------------------------
__global__ void zero_small_kernel() {
    int idx = blockIdx.x * blockDim.x + threadIdx.x;
    if (idx == 0) g_cnt = 0;
    for (int i = idx; i < N_BEH * N_USER; i += gridDim.x * blockDim.x)
        g_S[i] = 0.0f;
    for (int i = idx; i < N_ITEM; i += gridDim.x * blockDim.x)
        g_mask[i] = 0;
}

__global__ void mask_kernel(const int* __restrict__ pos_items,
                            const int* __restrict__ neg_items) {
    int t = blockIdx.x * blockDim.x + threadIdx.x;
    if (t < BATCH) {
        g_mask[pos_items[t]] = 1;
        g_mask[neg_items[t]] = 1;
    }
}

__global__ void zero_A_masked_kernel() {
    int idx = blockIdx.x * blockDim.x + threadIdx.x;
    int row = idx >> 4;
    if (row >= N_BEH * N_ITEM) return;
    int i = row % N_ITEM;
    if (g_mask[i]) {
        float4* dst = (float4*)&g_A[(size_t)row * DIM] + (idx & 15);
        *dst = make_float4(0.f, 0.f, 0.f, 0.f);
    }
}

// ---------------------------------------------------------------------------
// 256-bit load helper (sm_100a): 8 consecutive floats, 32B-aligned.
// ---------------------------------------------------------------------------
__device__ __forceinline__ void ldg_v8(const float* p, float* r) {
    asm volatile("ld.global.v8.f32 {%0,%1,%2,%3,%4,%5,%6,%7}, [%8];"
                 : "=f"(r[0]), "=f"(r[1]), "=f"(r[2]), "=f"(r[3]),
                   "=f"(r[4]), "=f"(r[5]), "=f"(r[6]), "=f"(r[7])
                 : "l"(p));
}

// ---------------------------------------------------------------------------
// Pass A v6: 4 lanes/edge, 8 edges/warp, v8 loads, LINE-ALIGNED lane map.
// Lane sl loads floats [sl*8, sl*8+8) and [32+sl*8, 32+sl*8+8):
//   instruction 1 -> 128B line 0 of the row segment, instruction 2 -> line 1.
// One line per edge per LDG instruction (wavefront floor).
// ---------------------------------------------------------------------------
__global__ void edge_act_kernel(const float* __restrict__ user_emb,
                                const float* __restrict__ item_emb,
                                const float* __restrict__ alpha_w,
                                const float* __restrict__ alpha_b,
                                const int*   __restrict__ edge_index,
                                float* __restrict__ tpw,
                                float* __restrict__ aux) {
    const unsigned FULL = 0xffffffffu;
    int tid  = threadIdx.x;
    int lane = tid & 31;
    int sl   = lane & 3;                 // sub-lane within edge (0..3)
    size_t e = ((size_t)blockIdx.x * blockDim.x + tid) >> 2;   // edge id
    int b    = (int)(e / NE);            // uniform per warp
    int el   = (int)(e - (size_t)b * NE);

    const int* ei = edge_index + (size_t)b * 2 * NE;
    int u = ei[el];
    int i = ei[NE + el];

    const float* up = &user_emb[(size_t)u * (N_BEH * DIM) + b * DIM + sl * 8];
    const float* ip = &item_emb[(size_t)i * (N_BEH * DIM) + b * DIM + sl * 8];
    const float* ap = &alpha_w[b * DIM + sl * 8];

    float uv[16], iv[16], av[16];
    ldg_v8(up,      uv);          // line 0 of the 256B segment
    ldg_v8(ip,      iv);
    ldg_v8(ap,      av);
    ldg_v8(up + 32, uv + 8);      // line 1
    ldg_v8(ip + 32, iv + 8);
    ldg_v8(ap + 32, av + 8);

    float z = 0.f, a2 = 0.f;
    #pragma unroll
    for (int k = 0; k < 16; k++) {
        float d = fabsf(uv[k] - iv[k]);
        z  += d * av[k];
        a2 += d * d;
    }

    #pragma unroll
    for (int o = 2; o; o >>= 1) {
        z  += __shfl_xor_sync(FULL, z,  o);
        a2 += __shfl_xor_sync(FULL, a2, o);
    }

    z += alpha_b[b];
    float act = (z > 0.0f) ? z : (expf(z) - 1.0f);   // elu(alpha=1)
    float ev  = expf(act);                           // bounded; no max shift
    if (sl == 0) {
        tpw[(size_t)b * NE + el] = ev;
        aux[(size_t)b * NE + el] = a2;
        float* dst = &g_S[b * N_USER + u];
        asm volatile("red.global.add.f32 [%0], %1;" :: "l"(dst), "f"(ev) : "memory");
    }
}

// ---------------------------------------------------------------------------
// Normalize tpw (4 edges/thread, vectorized) + compact masked edges.
// Tail-guarded; all warp shuffles unconditional.
// ---------------------------------------------------------------------------
__global__ void norm_compact_kernel(const int* __restrict__ edge_index,
                                    float* __restrict__ tpw) {
    const unsigned FULL = 0xffffffffu;
    int t4 = blockIdx.x * blockDim.x + threadIdx.x;
    int idx = t4 * 4;
    bool valid = (idx < NE_ALL);

    int b = 0, e = 0;
    int4 uu = make_int4(0, 0, 0, 0), ii = make_int4(0, 0, 0, 0);
    float4 w = make_float4(0.f, 0.f, 0.f, 0.f);
    int m0 = 0, m1 = 0, m2 = 0, m3 = 0;

    if (valid) {
        b = idx / NE;
        e = idx - b * NE;
        const int* ei = edge_index + (size_t)b * 2 * NE;
        uu = *(const int4*)&ei[e];
        ii = *(const int4*)&ei[NE + e];
        float4 tv = *(const float4*)&tpw[idx];
        const float* Sb = &g_S[b * N_USER];
        w.x = tv.x / Sb[uu.x];
        w.y = tv.y / Sb[uu.y];
        w.z = tv.z / Sb[uu.z];
        w.w = tv.w / Sb[uu.w];
        *(float4*)&tpw[idx] = w;
        m0 = g_mask[ii.x]; m1 = g_mask[ii.y]; m2 = g_mask[ii.z]; m3 = g_mask[ii.w];
    }
    int cnt = m0 + m1 + m2 + m3;

    int lane = threadIdx.x & 31;
    int pre = cnt;
    #pragma unroll
    for (int o = 1; o < 32; o <<= 1) {
        int v = __shfl_up_sync(FULL, pre, o);
        if (lane >= o) pre += v;
    }
    int total = __shfl_sync(FULL, pre, 31);
    int excl  = pre - cnt;
    int base = 0;
    if (lane == 31 && total) base = atomicAdd(&g_cnt, total);
    base = __shfl_sync(FULL, base, 31);

    if (valid && cnt) {
        int off = base + excl;
        int us[4] = {uu.x, uu.y, uu.z, uu.w};
        int is[4] = {ii.x, ii.y, ii.z, ii.w};
        float ws[4] = {w.x, w.y, w.z, w.w};
        int ms[4] = {m0, m1, m2, m3};
        #pragma unroll
        for (int j = 0; j < 4; j++) {
            if (ms[j]) {
                g_cu[off]  = us[j] * (N_BEH * DIM) + b * DIM;
                g_cib[off] = (b * N_ITEM + is[j]) * DIM;
                g_cw[off]  = ws[j];
                off++;
            }
        }
    }
}

// ---------------------------------------------------------------------------
// Dense scatter over compacted list.
// ---------------------------------------------------------------------------
__global__ void scatter2_kernel(const float* __restrict__ user_emb) {
    int l    = threadIdx.x & 15;
    int slot = (blockIdx.x * blockDim.x + threadIdx.x) >> 4;
    int stride = (gridDim.x * blockDim.x) >> 4;
    int total = g_cnt;
    for (int e = slot; e < total; e += stride) {
        int uoff = g_cu[e];
        int aoff = g_cib[e];
        float w  = g_cw[e];
        float4 uv = *(const float4*)&user_emb[(size_t)uoff + 4 * l];
        float* dst = &g_A[(size_t)aoff + 4 * l];
        asm volatile("red.global.add.v4.f32 [%0], {%1,%2,%3,%4};"
                     :: "l"(dst), "f"(w * uv.x), "f"(w * uv.y),
                        "f"(w * uv.z), "f"(w * uv.w) : "memory");
    }
}

// ---------------------------------------------------------------------------
// Pass C: 8 rows/block, 128 threads, 4 rows/thread in matmul phases.
// ---------------------------------------------------------------------------
#define ROWS_PB 8
#define ROW_F   816
// layout per row: xs@0, qs@192(=ao), ks@384(=hh), vs@576, sc@768, mus@804, rss@808

__global__ __launch_bounds__(128)
void attn_kernel(const float* __restrict__ user_emb,
                 const float* __restrict__ item_emb,
                 const float* __restrict__ wq, const float* __restrict__ bq,
                 const float* __restrict__ wk, const float* __restrict__ bk,
                 const float* __restrict__ wv, const float* __restrict__ bv,
                 const float* __restrict__ wo, const float* __restrict__ bo,
                 const float* __restrict__ lng, const float* __restrict__ lnb,
                 const int* __restrict__ users,
                 const int* __restrict__ pos_items,
                 const int* __restrict__ neg_items,
                 float* __restrict__ emb_out) {
    __shared__ float sm[ROWS_PB * ROW_F];
    int t = threadIdx.x & 63;
    int g = threadIdx.x >> 6;
    int row0 = blockIdx.x * ROWS_PB;

    #pragma unroll
    for (int r = 0; r < 4; r++) {
        int lr  = g * 4 + r;
        int row = row0 + lr;
        int node; bool is_user;
        if (row < BATCH)          { node = users[row];                 is_user = true;  }
        else if (row < 2 * BATCH) { node = pos_items[row - BATCH];     is_user = false; }
        else                      { node = neg_items[row - 2 * BATCH]; is_user = false; }
        float* xs = sm + lr * ROW_F;
        #pragma unroll
        for (int beh = 0; beh < 3; beh++) {
            float v;
            if (is_user) {
                v = user_emb[(size_t)node * (N_BEH * DIM) + beh * DIM + t];
            } else {
                v = 2.0f * g_A[((size_t)beh * N_ITEM + node) * DIM + t]
                    + item_emb[(size_t)node * (N_BEH * DIM) + beh * DIM + t];
            }
            xs[beh * 64 + t] = v;
        }
    }
    __syncthreads();

    {
        float aq[4][3], ak[4][3], av[4][3];
        float bqv = bq[t], bkv = bk[t], bvv = bv[t];
        #pragma unroll
        for (int r = 0; r < 4; r++)
            #pragma unroll
            for (int beh = 0; beh < 3; beh++) {
                aq[r][beh] = bqv; ak[r][beh] = bkv; av[r][beh] = bvv;
            }
        #pragma unroll 4
        for (int d4 = 0; d4 < 64; d4 += 4) {
            float w1[4], w2[4], w3[4];
            #pragma unroll
            for (int k = 0; k < 4; k++) {
                w1[k] = wq[(d4 + k) * 64 + t];
                w2[k] = wk[(d4 + k) * 64 + t];
                w3[k] = wv[(d4 + k) * 64 + t];
            }
            #pragma unroll
            for (int r = 0; r < 4; r++) {
                const float* xr = sm + (g * 4 + r) * ROW_F;
                #pragma unroll
                for (int beh = 0; beh < 3; beh++) {
                    float4 x = *(const float4*)&xr[beh * 64 + d4];
                    aq[r][beh] += x.x * w1[0] + x.y * w1[1] + x.z * w1[2] + x.w * w1[3];
                    ak[r][beh] += x.x * w2[0] + x.y * w2[1] + x.z * w2[2] + x.w * w2[3];
                    av[r][beh] += x.x * w3[0] + x.y * w3[1] + x.z * w3[2] + x.w * w3[3];
                }
            }
        }
        #pragma unroll
        for (int r = 0; r < 4; r++) {
            float* base = sm + (g * 4 + r) * ROW_F;
            #pragma unroll
            for (int beh = 0; beh < 3; beh++) {
                base[192 + beh * 64 + t] = aq[r][beh];
                base[384 + beh * 64 + t] = ak[r][beh];
                base[576 + beh * 64 + t] = av[r][beh];
            }
        }
    }
    __syncthreads();

    for (int uu = threadIdx.x; uu < ROWS_PB * 36; uu += 128) {
        int lr  = uu / 36;
        int rem = uu - lr * 36;
        int h   = rem / 9;
        int qb  = (rem % 9) / 3;
        int kb  = rem % 3;
        float* base = sm + lr * ROW_F;
        float s = 0.0f;
        #pragma unroll
        for (int j = 0; j < 16; j++)
            s += base[192 + qb * 64 + h * 16 + j] * base[384 + kb * 64 + h * 16 + j];
        base[768 + rem] = s * 0.25f;
    }
    __syncthreads();

    if (threadIdx.x < ROWS_PB * 12) {
        int lr = threadIdx.x / 12;
        int p  = threadIdx.x - lr * 12;
        float* sc = sm + lr * ROW_F + 768 + p * 3;
        float s0 = sc[0], s1 = sc[1], s2 = sc[2];
        float m = fmaxf(s0, fmaxf(s1, s2));
        float e0 = expf(s0 - m), e1 = expf(s1 - m), e2 = expf(s2 - m);
        float inv = 1.0f / (e0 + e1 + e2);
        sc[0] = e0 * inv; sc[1] = e1 * inv; sc[2] = e2 * inv;
    }
    __syncthreads();

    for (int uu = threadIdx.x; uu < ROWS_PB * 64; uu += 128) {
        int lr = uu >> 6;
        int tt = uu & 63;
        int h  = tt >> 4;
        float* base = sm + lr * ROW_F;
        #pragma unroll
        for (int qb = 0; qb < 3; qb++) {
            float a = 0.0f;
            #pragma unroll
            for (int kb = 0; kb < 3; kb++)
                a += base[768 + h * 9 + qb * 3 + kb] * base[576 + kb * 64 + tt];
            base[192 + qb * 64 + tt] = a;
        }
    }
    __syncthreads();

    {
        float acc[4][3];
        float bov = bo[t];
        #pragma unroll
        for (int r = 0; r < 4; r++)
            #pragma unroll
            for (int beh = 0; beh < 3; beh++) acc[r][beh] = bov;
        #pragma unroll 4
        for (int d4 = 0; d4 < 64; d4 += 4) {
            float w[4];
            #pragma unroll
            for (int k = 0; k < 4; k++) w[k] = wo[(d4 + k) * 64 + t];
            #pragma unroll
            for (int r = 0; r < 4; r++) {
                const float* base = sm + (g * 4 + r) * ROW_F;
                #pragma unroll
                for (int beh = 0; beh < 3; beh++) {
                    float4 a = *(const float4*)&base[192 + beh * 64 + d4];
                    acc[r][beh] += a.x * w[0] + a.y * w[1] + a.z * w[2] + a.w * w[3];
                }
            }
        }
        __syncthreads();
        #pragma unroll
        for (int r = 0; r < 4; r++) {
            float* base = sm + (g * 4 + r) * ROW_F;
            #pragma unroll
            for (int beh = 0; beh < 3; beh++)
                base[384 + beh * 64 + t] = acc[r][beh] + base[beh * 64 + t];
        }
    }
    __syncthreads();

    if (threadIdx.x < ROWS_PB * 3) {
        int lr  = threadIdx.x / 3;
        int beh = threadIdx.x - lr * 3;
        float* hh = sm + lr * ROW_F + 384 + beh * 64;
        float s = 0.0f;
        #pragma unroll 8
        for (int j = 0; j < 64; j++) s += hh[j];
        float mu = s * (1.0f / 64.0f);
        float v = 0.0f;
        #pragma unroll 8
        for (int j = 0; j < 64; j++) {
            float dd = hh[j] - mu;
            v += dd * dd;
        }
        v *= (1.0f / 64.0f);
        sm[lr * ROW_F + 804 + beh] = mu;
        sm[lr * ROW_F + 808 + beh] = rsqrtf(v + LN_EPS);
    }
    __syncthreads();

    for (int uu = threadIdx.x; uu < ROWS_PB * 64; uu += 128) {
        int lr = uu >> 6;
        int tt = uu & 63;
        float* base = sm + lr * ROW_F;
        float gg = lng[tt], bb = lnb[tt];
        float gsum = 0.0f;
        #pragma unroll
        for (int beh = 0; beh < 3; beh++)
            gsum += (base[384 + beh * 64 + tt] - base[804 + beh]) * base[808 + beh] * gg + bb;
        emb_out[(size_t)(row0 + lr) * 64 + tt] = gsum;
    }
}

// ---------------------------------------------------------------------------
extern "C" void kernel_launch(void* const* d_in, const int* in_sizes, int n_in,
                              void* d_out, int out_size) {
    const float* user_emb = (const float*)d_in[0];
    const float* item_emb = (const float*)d_in[1];
    const float* alpha_w  = (const float*)d_in[2];
    const float* alpha_b  = (const float*)d_in[3];
    const float* wq = (const float*)d_in[4];
    const float* bq = (const float*)d_in[5];
    const float* wk = (const float*)d_in[6];
    const float* bk = (const float*)d_in[7];
    const float* wv = (const float*)d_in[8];
    const float* bv = (const float*)d_in[9];
    const float* wo = (const float*)d_in[10];
    const float* bo = (const float*)d_in[11];
    const float* lng = (const float*)d_in[12];
    const float* lnb = (const float*)d_in[13];
    const int* edge_index = (const int*)d_in[14];
    const int* users      = (const int*)d_in[15];
    const int* pos_items  = (const int*)d_in[16];
    const int* neg_items  = (const int*)d_in[17];

    float* out     = (float*)d_out;
    float* emb_out = out;
    float* tpw     = out + (size_t)3 * BATCH * DIM;
    float* aux     = tpw + (size_t)N_BEH * NE;

    zero_small_kernel<<<256, 256>>>();
    mask_kernel<<<(BATCH + 255) / 256, 256>>>(pos_items, neg_items);
    zero_A_masked_kernel<<<(N_BEH * N_ITEM * 16 + 255) / 256, 256>>>();

    edge_act_kernel<<<(size_t)NE_ALL * 4 / 256, 256>>>(user_emb, item_emb,
                                                       alpha_w, alpha_b,
                                                       edge_index, tpw, aux);

    norm_compact_kernel<<<(NE_ALL / 4 + 255) / 256, 256>>>(edge_index, tpw);

    scatter2_kernel<<<4096, 256>>>(user_emb);

    attn_kernel<<<(3 * BATCH) / ROWS_PB, 128>>>(user_emb, item_emb,
                                                wq, bq, wk, bk, wv, bv, wo, bo,
                                                lng, lnb, users, pos_items, neg_items,
                                                emb_out);
}